// round 2
// baseline (speedup 1.0000x reference)
#include <cuda_runtime.h>

#define M_ROWS 32768
#define ZC     512
#define DDIM   256
#define K_CODES 8192

// ---------------- device scratch (no allocations allowed) ----------------
__device__ float  g_h[M_ROWS * DDIM];   // 32 MB: h = x@W + b
__device__ float  g_en[K_CODES];        // ||c_k||^2  (fp32-rounded exact)
__device__ float  g_zn[M_ROWS];         // ||h_i||^2  (fp32-rounded exact)
__device__ int    g_idx[M_ROWS];        // argmin index per row
__device__ double g_part[4096];         // deterministic loss partials

// ---------------- packed f32x2 helpers ----------------
__device__ __forceinline__ unsigned long long pk2(float lo, float hi) {
    unsigned long long r;
    asm("mov.b64 %0, {%1, %2};" : "=l"(r) : "f"(lo), "f"(hi));
    return r;
}
__device__ __forceinline__ void fma2(unsigned long long &d,
                                     unsigned long long a,
                                     unsigned long long b) {
    asm("fma.rn.f32x2 %0, %1, %2, %0;" : "+l"(d) : "l"(a), "l"(b));
}
__device__ __forceinline__ float2 up2(unsigned long long v) {
    float2 f;
    asm("mov.b64 {%0, %1}, %2;" : "=f"(f.x), "=f"(f.y) : "l"(v));
    return f;
}

// ---------------- kernel 0a: codebook squared norms (fp64 -> fp32) ----------------
__global__ void prep_cb_kernel(const float* __restrict__ cb) {
    int warp = (blockIdx.x * blockDim.x + threadIdx.x) >> 5;
    int lane = threadIdx.x & 31;
    if (warp < K_CODES) {
        const float* row = cb + (size_t)warp * DDIM;
        double s = 0.0;
        #pragma unroll
        for (int d = 0; d < DDIM / 32; d++) {
            double v = (double)row[lane + 32 * d];
            s += v * v;
        }
        #pragma unroll
        for (int o = 16; o; o >>= 1) s += __shfl_xor_sync(0xffffffffu, s, o);
        if (lane == 0) g_en[warp] = (float)s;
    }
}

// ---------------- kernel 0b: h row squared norms (fp64 -> fp32) ----------------
__global__ void prep_zn_kernel() {
    int warp = (blockIdx.x * blockDim.x + threadIdx.x) >> 5;
    int lane = threadIdx.x & 31;
    if (warp < M_ROWS) {
        const float* row = g_h + (size_t)warp * DDIM;
        double s = 0.0;
        #pragma unroll
        for (int d = 0; d < DDIM / 32; d++) {
            double v = (double)row[lane + 32 * d];
            s += v * v;
        }
        #pragma unroll
        for (int o = 16; o; o >>= 1) s += __shfl_xor_sync(0xffffffffu, s, o);
        if (lane == 0) g_zn[warp] = (float)s;
    }
}

// ---------------- kernel 1: h = x @ W + b  (M=32768, K=512, N=256) ----------------
// 128x128 tile, 256 threads, 8x8 per thread, f32x2 packed FMAs, double-buffered smem.
__global__ __launch_bounds__(256) void gemm1_kernel(const float* __restrict__ X,
                                                    const float* __restrict__ Wm,
                                                    const float* __restrict__ bias) {
    __shared__ __align__(16) float sm[2 * 16 * 132 * 2]; // As[2][16][132] then Bs[2][16][132]
    float* As = sm;
    float* Bs = sm + 2 * 16 * 132;
    const int m0 = blockIdx.x * 128;
    const int n0 = blockIdx.y * 128;
    const int tid = threadIdx.x;
    const int ty = tid >> 4, tx = tid & 15;

    unsigned long long acc[8][4];
    #pragma unroll
    for (int i = 0; i < 8; i++)
        #pragma unroll
        for (int j = 0; j < 4; j++) acc[i][j] = 0ull;

    const int ar = tid >> 2;            // 0..63
    const int ac = (tid & 3) << 2;      // 0,4,8,12
    const int kb = tid >> 5;            // 0..7
    const int n4 = (tid & 31) << 2;     // 0..124

    const int NS = ZC / 16;             // 32 stages
    float4 a0r, a1r, b0r, b1r;

    {
        a0r = *(const float4*)(X + (size_t)(m0 + ar) * ZC + ac);
        a1r = *(const float4*)(X + (size_t)(m0 + ar + 64) * ZC + ac);
        b0r = *(const float4*)(Wm + (size_t)kb * DDIM + n0 + n4);
        b1r = *(const float4*)(Wm + (size_t)(kb + 8) * DDIM + n0 + n4);
        const float* ap0 = (const float*)&a0r;
        const float* ap1 = (const float*)&a1r;
        #pragma unroll
        for (int j = 0; j < 4; j++) {
            As[(ac + j) * 132 + ar]      = ap0[j];
            As[(ac + j) * 132 + ar + 64] = ap1[j];
        }
        *(float4*)&Bs[kb * 132 + n4]       = b0r;
        *(float4*)&Bs[(kb + 8) * 132 + n4] = b1r;
    }
    __syncthreads();

    #pragma unroll 1
    for (int s = 0; s < NS; s++) {
        const int buf = s & 1;
        const bool more = (s + 1 < NS);
        if (more) {
            const int kk = (s + 1) << 4;
            a0r = *(const float4*)(X + (size_t)(m0 + ar) * ZC + kk + ac);
            a1r = *(const float4*)(X + (size_t)(m0 + ar + 64) * ZC + kk + ac);
            b0r = *(const float4*)(Wm + (size_t)(kk + kb) * DDIM + n0 + n4);
            b1r = *(const float4*)(Wm + (size_t)(kk + kb + 8) * DDIM + n0 + n4);
        }
        const float* Ab = As + buf * 16 * 132;
        const float* Bb = Bs + buf * 16 * 132;
        #pragma unroll
        for (int k = 0; k < 16; k++) {
            float4 av0 = *(const float4*)&Ab[k * 132 + ty * 8];
            float4 av1 = *(const float4*)&Ab[k * 132 + ty * 8 + 4];
            ulonglong2 bb0 = *(const ulonglong2*)&Bb[k * 132 + tx * 8];
            ulonglong2 bb1 = *(const ulonglong2*)&Bb[k * 132 + tx * 8 + 4];
            float av[8] = {av0.x, av0.y, av0.z, av0.w, av1.x, av1.y, av1.z, av1.w};
            #pragma unroll
            for (int i = 0; i < 8; i++) {
                unsigned long long ap = pk2(av[i], av[i]);
                fma2(acc[i][0], ap, bb0.x);
                fma2(acc[i][1], ap, bb0.y);
                fma2(acc[i][2], ap, bb1.x);
                fma2(acc[i][3], ap, bb1.y);
            }
        }
        __syncthreads();
        if (more) {
            const float* ap0 = (const float*)&a0r;
            const float* ap1 = (const float*)&a1r;
            float* An = As + (buf ^ 1) * 16 * 132;
            float* Bn = Bs + (buf ^ 1) * 16 * 132;
            #pragma unroll
            for (int j = 0; j < 4; j++) {
                An[(ac + j) * 132 + ar]      = ap0[j];
                An[(ac + j) * 132 + ar + 64] = ap1[j];
            }
            *(float4*)&Bn[kb * 132 + n4]       = b0r;
            *(float4*)&Bn[(kb + 8) * 132 + n4] = b1r;
            __syncthreads();
        }
    }

    #pragma unroll
    for (int j = 0; j < 4; j++) {
        const int col = n0 + tx * 8 + 2 * j;
        const float bv0 = bias[col];
        const float bv1 = bias[col + 1];
        #pragma unroll
        for (int i = 0; i < 8; i++) {
            float2 v = up2(acc[i][j]);
            const int row = m0 + ty * 8 + i;
            g_h[(size_t)row * DDIM + col]     = v.x + bv0;
            g_h[(size_t)row * DDIM + col + 1] = v.y + bv1;
        }
    }
}

// ---------------- kernel 2: streaming distances + argmin ----------------
// Per CTA: 128 rows vs all 8192 codes.
// Replicates reference numerics: A = fl(znorm + enorm); d = fl(A - 2*dot).
// argmin over d, ties -> lowest code index (jnp.argmin first-occurrence).
__global__ __launch_bounds__(256) void gemm2_kernel(const float* __restrict__ cb) {
    __shared__ __align__(16) float sm[2 * 16 * 132 * 2];
    float* As = sm;
    float* Bs = sm + 2 * 16 * 132;
    const int m0 = blockIdx.x * 128;
    const int tid = threadIdx.x;
    const int ty = tid >> 4, tx = tid & 15;

    unsigned long long acc[8][4];
    #pragma unroll
    for (int i = 0; i < 8; i++)
        #pragma unroll
        for (int j = 0; j < 4; j++) acc[i][j] = 0ull;

    float best[8];
    int   bidx[8];
    float zn[8];
    #pragma unroll
    for (int i = 0; i < 8; i++) {
        best[i] = 3.402823466e38f;          // minimize d
        bidx[i] = 0;
        zn[i] = g_zn[m0 + ty * 8 + i];
    }

    const int r1 = tid >> 2;        // 0..63
    const int c1 = (tid & 3) << 2;  // 0,4,8,12
    const float* Abase = g_h + (size_t)m0 * DDIM;

    const int NSTAGES = (K_CODES / 128) * 16;  // 64 chunks x 16 k-stages
    float4 a0r, a1r, b0r, b1r;

    {
        a0r = *(const float4*)(Abase + (size_t)r1 * DDIM + c1);
        a1r = *(const float4*)(Abase + (size_t)(r1 + 64) * DDIM + c1);
        b0r = *(const float4*)(cb + (size_t)r1 * DDIM + c1);
        b1r = *(const float4*)(cb + (size_t)(r1 + 64) * DDIM + c1);
        const float* ap0 = (const float*)&a0r;
        const float* ap1 = (const float*)&a1r;
        const float* bp0 = (const float*)&b0r;
        const float* bp1 = (const float*)&b1r;
        #pragma unroll
        for (int j = 0; j < 4; j++) {
            As[(c1 + j) * 132 + r1]      = ap0[j];
            As[(c1 + j) * 132 + r1 + 64] = ap1[j];
            Bs[(c1 + j) * 132 + r1]      = bp0[j];
            Bs[(c1 + j) * 132 + r1 + 64] = bp1[j];
        }
    }
    __syncthreads();

    #pragma unroll 1
    for (int s = 0; s < NSTAGES; s++) {
        const int buf = s & 1;
        const bool more = (s + 1 < NSTAGES);
        if (more) {
            const int sn = s + 1;
            const int kk = (sn & 15) << 4;
            const int crow = (sn >> 4) << 7;
            a0r = *(const float4*)(Abase + (size_t)r1 * DDIM + kk + c1);
            a1r = *(const float4*)(Abase + (size_t)(r1 + 64) * DDIM + kk + c1);
            b0r = *(const float4*)(cb + (size_t)(crow + r1) * DDIM + kk + c1);
            b1r = *(const float4*)(cb + (size_t)(crow + r1 + 64) * DDIM + kk + c1);
        }
        const float* Ab = As + buf * 16 * 132;
        const float* Bb = Bs + buf * 16 * 132;
        #pragma unroll
        for (int k = 0; k < 16; k++) {
            float4 av0 = *(const float4*)&Ab[k * 132 + ty * 8];
            float4 av1 = *(const float4*)&Ab[k * 132 + ty * 8 + 4];
            ulonglong2 bb0 = *(const ulonglong2*)&Bb[k * 132 + tx * 8];
            ulonglong2 bb1 = *(const ulonglong2*)&Bb[k * 132 + tx * 8 + 4];
            float av[8] = {av0.x, av0.y, av0.z, av0.w, av1.x, av1.y, av1.z, av1.w};
            #pragma unroll
            for (int i = 0; i < 8; i++) {
                unsigned long long ap = pk2(av[i], av[i]);
                fma2(acc[i][0], ap, bb0.x);
                fma2(acc[i][1], ap, bb0.y);
                fma2(acc[i][2], ap, bb1.x);
                fma2(acc[i][3], ap, bb1.y);
            }
        }
        if ((s & 15) == 15) {
            // finished D=256 for this chunk of 128 codes: fold into running argmin
            const int n0c = (s >> 4) << 7;
            const int cb0 = n0c + tx * 8;
            #pragma unroll
            for (int j = 0; j < 4; j++) {
                const float en0 = g_en[cb0 + 2 * j];
                const float en1 = g_en[cb0 + 2 * j + 1];
                #pragma unroll
                for (int i = 0; i < 8; i++) {
                    float2 sc = up2(acc[i][j]);
                    // reference rounding: A = fl(zn + en); d = fl(A - 2*dot)
                    const float A0 = __fadd_rn(zn[i], en0);
                    const float A1 = __fadd_rn(zn[i], en1);
                    const float d0 = __fadd_rn(A0, -2.0f * sc.x);
                    const float d1 = __fadd_rn(A1, -2.0f * sc.y);
                    if (d0 < best[i]) { best[i] = d0; bidx[i] = cb0 + 2 * j; }
                    if (d1 < best[i]) { best[i] = d1; bidx[i] = cb0 + 2 * j + 1; }
                    acc[i][j] = 0ull;
                }
            }
        }
        __syncthreads();
        if (more) {
            const float* ap0 = (const float*)&a0r;
            const float* ap1 = (const float*)&a1r;
            const float* bp0 = (const float*)&b0r;
            const float* bp1 = (const float*)&b1r;
            float* An = As + (buf ^ 1) * 16 * 132;
            float* Bn = Bs + (buf ^ 1) * 16 * 132;
            #pragma unroll
            for (int j = 0; j < 4; j++) {
                An[(c1 + j) * 132 + r1]      = ap0[j];
                An[(c1 + j) * 132 + r1 + 64] = ap1[j];
                Bn[(c1 + j) * 132 + r1]      = bp0[j];
                Bn[(c1 + j) * 132 + r1 + 64] = bp1[j];
            }
            __syncthreads();
        }
    }

    // cross-thread argmin reduction (16 threads per row), tie-break lowest index
    __syncthreads();
    float* rv = sm;                 // [128][16] floats
    int*   ri = (int*)(sm + 2048);  // [128][16] ints
    #pragma unroll
    for (int i = 0; i < 8; i++) {
        const int m = ty * 8 + i;
        rv[m * 16 + tx] = best[i];
        ri[m * 16 + tx] = bidx[i];
    }
    __syncthreads();
    if (tid < 128) {
        float bv = rv[tid * 16];
        int   bi = ri[tid * 16];
        #pragma unroll
        for (int t2 = 1; t2 < 16; t2++) {
            const float v = rv[tid * 16 + t2];
            const int  ix = ri[tid * 16 + t2];
            if (v < bv || (v == bv && ix < bi)) { bv = v; bi = ix; }
        }
        g_idx[m0 + tid] = bi;
    }
}

// ---------------- kernel 3: gather quant + deterministic loss partials ----------------
__global__ void gather_loss_kernel(const float* __restrict__ cb, float* __restrict__ out) {
    const int b = blockIdx.x;        // 4096 blocks x 2048 elements
    const int t = threadIdx.x;       // 512 threads
    const int base = b * 2048;
    double s = 0.0;
    #pragma unroll
    for (int e = 0; e < 4; e++) {
        const int g = base + t + e * 512;
        const int row = g >> 8;
        const int d = g & 255;
        const int idx = g_idx[row];
        const float c = cb[(size_t)idx * DDIM + d];
        const float h = g_h[g];
        out[g] = c;                  // straight-through: quant == zq == codebook[idx]
        const double diff = (double)(c - h);
        s += diff * diff;
    }
    __shared__ double red[512];
    red[t] = s;
    __syncthreads();
    for (int o = 256; o; o >>= 1) {
        if (t < o) red[t] += red[t + o];
        __syncthreads();
    }
    if (t == 0) g_part[b] = red[0];
}

// ---------------- kernel 4: finalize loss ----------------
__global__ void finalize_kernel(float* __restrict__ out, int has_loss) {
    __shared__ double red[1024];
    const int t = threadIdx.x;
    double s = 0.0;
    for (int i = t; i < 4096; i += 1024) s += g_part[i];
    red[t] = s;
    __syncthreads();
    for (int o = 512; o; o >>= 1) {
        if (t < o) red[t] += red[t + o];
        __syncthreads();
    }
    if (t == 0 && has_loss) {
        // emb_loss = 0.25*mean + 1.0*mean = 1.25 * mean((zq-h)^2)
        out[(size_t)M_ROWS * DDIM] =
            (float)(1.25 * red[0] / (double)((size_t)M_ROWS * DDIM));
    }
}

// ---------------- host launcher ----------------
extern "C" void kernel_launch(void* const* d_in, const int* in_sizes, int n_in,
                              void* d_out, int out_size) {
    const float* x = nullptr;
    const float* W = nullptr;
    const float* b = nullptr;
    const float* cb = nullptr;
    for (int i = 0; i < n_in; i++) {
        switch (in_sizes[i]) {
            case M_ROWS * ZC:   x = (const float*)d_in[i]; break;   // 16,777,216
            case ZC * DDIM:     W = (const float*)d_in[i]; break;   // 131,072
            case DDIM:          b = (const float*)d_in[i]; break;   // 256
            case K_CODES * DDIM: cb = (const float*)d_in[i]; break; // 2,097,152
            default: break;
        }
    }
    float* out = (float*)d_out;
    const int has_loss = (out_size > M_ROWS * DDIM) ? 1 : 0;

    prep_cb_kernel<<<K_CODES / 8, 256>>>(cb);
    dim3 g1(M_ROWS / 128, DDIM / 128);
    gemm1_kernel<<<g1, 256>>>(x, W, b);
    prep_zn_kernel<<<M_ROWS / 8, 256>>>();
    gemm2_kernel<<<M_ROWS / 128, 256>>>(cb);
    gather_loss_kernel<<<4096, 512>>>(cb, out);
    finalize_kernel<<<1, 1024>>>(out, has_loss);
}

// round 7
// speedup vs baseline: 2.6854x; 2.6854x over previous
#include <cuda_runtime.h>
#include <cuda_fp16.h>
#include <cstdint>

#define M_ROWS 32768
#define ZC     512
#define DDIM   256
#define K_CODES 8192

// ---------------- device scratch ----------------
__device__ float  g_h[M_ROWS * DDIM];     // 32 MB fp32 h
__device__ __half g_ahi[M_ROWS * DDIM];   // 16 MB
__device__ __half g_alo[M_ROWS * DDIM];   // 16 MB
__device__ __half g_bhi[K_CODES * DDIM];  // 4 MB
__device__ __half g_blo[K_CODES * DDIM];  // 4 MB
__device__ float  g_en[K_CODES];
__device__ float  g_zn[M_ROWS];
__device__ int    g_idx[M_ROWS];
__device__ double g_part[4096];

// ---------------- f32x2 helpers (gemm1) ----------------
__device__ __forceinline__ unsigned long long pk2(float lo, float hi) {
    unsigned long long r;
    asm("mov.b64 %0, {%1, %2};" : "=l"(r) : "f"(lo), "f"(hi));
    return r;
}
__device__ __forceinline__ void fma2(unsigned long long &d,
                                     unsigned long long a,
                                     unsigned long long b) {
    asm("fma.rn.f32x2 %0, %1, %2, %0;" : "+l"(d) : "l"(a), "l"(b));
}
__device__ __forceinline__ float2 up2(unsigned long long v) {
    float2 f;
    asm("mov.b64 {%0, %1}, %2;" : "=f"(f.x), "=f"(f.y) : "l"(v));
    return f;
}

__device__ __forceinline__ uint32_t smem_u32(const void* p) {
    uint32_t a;
    asm("{ .reg .u64 t; cvta.to.shared.u64 t, %1; cvt.u32.u64 %0, t; }" : "=r"(a) : "l"(p));
    return a;
}
__device__ __forceinline__ uint32_t sw128(uint32_t b) { return b ^ ((b >> 3) & 0x70); }

#define LDSM_X4(r0, r1, r2, r3, addr) \
    asm volatile("ldmatrix.sync.aligned.m8n8.x4.shared.b16 {%0,%1,%2,%3}, [%4];" \
                 : "=r"(r0), "=r"(r1), "=r"(r2), "=r"(r3) : "r"(addr))

__device__ __forceinline__ void mma16816(float* c, const uint32_t* a, const uint32_t* b) {
    asm volatile("mma.sync.aligned.m16n8k16.row.col.f32.f16.f16.f32 "
                 "{%0,%1,%2,%3}, {%4,%5,%6,%7}, {%8,%9}, {%0,%1,%2,%3};"
                 : "+f"(c[0]), "+f"(c[1]), "+f"(c[2]), "+f"(c[3])
                 : "r"(a[0]), "r"(a[1]), "r"(a[2]), "r"(a[3]), "r"(b[0]), "r"(b[1]));
}

// ---------------- kernel 0a: codebook norms ----------------
__global__ void prep_cb_kernel(const float* __restrict__ cb) {
    int warp = (blockIdx.x * blockDim.x + threadIdx.x) >> 5;
    int lane = threadIdx.x & 31;
    if (warp < K_CODES) {
        const float* row = cb + (size_t)warp * DDIM;
        double s = 0.0;
        #pragma unroll
        for (int d = 0; d < DDIM / 32; d++) {
            double v = (double)row[lane + 32 * d];
            s += v * v;
        }
        #pragma unroll
        for (int o = 16; o; o >>= 1) s += __shfl_xor_sync(0xffffffffu, s, o);
        if (lane == 0) g_en[warp] = (float)s;
    }
}

// ---------------- kernel 0b: h row norms ----------------
__global__ void prep_zn_kernel() {
    int warp = (blockIdx.x * blockDim.x + threadIdx.x) >> 5;
    int lane = threadIdx.x & 31;
    if (warp < M_ROWS) {
        const float* row = g_h + (size_t)warp * DDIM;
        double s = 0.0;
        #pragma unroll
        for (int d = 0; d < DDIM / 32; d++) {
            double v = (double)row[lane + 32 * d];
            s += v * v;
        }
        #pragma unroll
        for (int o = 16; o; o >>= 1) s += __shfl_xor_sync(0xffffffffu, s, o);
        if (lane == 0) g_zn[warp] = (float)s;
    }
}

// ---------------- kernel 1: h = x@W + b (fp32, f32x2) ----------------
__global__ __launch_bounds__(256) void gemm1_kernel(const float* __restrict__ X,
                                                    const float* __restrict__ Wm,
                                                    const float* __restrict__ bias) {
    __shared__ __align__(16) float sm[2 * 16 * 132 * 2];
    float* As = sm;
    float* Bs = sm + 2 * 16 * 132;
    const int m0 = blockIdx.x * 128;
    const int n0 = blockIdx.y * 128;
    const int tid = threadIdx.x;
    const int ty = tid >> 4, tx = tid & 15;

    unsigned long long acc[8][4];
    #pragma unroll
    for (int i = 0; i < 8; i++)
        #pragma unroll
        for (int j = 0; j < 4; j++) acc[i][j] = 0ull;

    const int ar = tid >> 2, ac = (tid & 3) << 2;
    const int kb = tid >> 5, n4 = (tid & 31) << 2;
    const int NS = ZC / 16;
    float4 a0r, a1r, b0r, b1r;
    {
        a0r = *(const float4*)(X + (size_t)(m0 + ar) * ZC + ac);
        a1r = *(const float4*)(X + (size_t)(m0 + ar + 64) * ZC + ac);
        b0r = *(const float4*)(Wm + (size_t)kb * DDIM + n0 + n4);
        b1r = *(const float4*)(Wm + (size_t)(kb + 8) * DDIM + n0 + n4);
        const float* ap0 = (const float*)&a0r;
        const float* ap1 = (const float*)&a1r;
        #pragma unroll
        for (int j = 0; j < 4; j++) {
            As[(ac + j) * 132 + ar] = ap0[j];
            As[(ac + j) * 132 + ar + 64] = ap1[j];
        }
        *(float4*)&Bs[kb * 132 + n4] = b0r;
        *(float4*)&Bs[(kb + 8) * 132 + n4] = b1r;
    }
    __syncthreads();
    #pragma unroll 1
    for (int s = 0; s < NS; s++) {
        const int buf = s & 1;
        const bool more = (s + 1 < NS);
        if (more) {
            const int kk = (s + 1) << 4;
            a0r = *(const float4*)(X + (size_t)(m0 + ar) * ZC + kk + ac);
            a1r = *(const float4*)(X + (size_t)(m0 + ar + 64) * ZC + kk + ac);
            b0r = *(const float4*)(Wm + (size_t)(kk + kb) * DDIM + n0 + n4);
            b1r = *(const float4*)(Wm + (size_t)(kk + kb + 8) * DDIM + n0 + n4);
        }
        const float* Ab = As + buf * 16 * 132;
        const float* Bb = Bs + buf * 16 * 132;
        #pragma unroll
        for (int k = 0; k < 16; k++) {
            float4 av0 = *(const float4*)&Ab[k * 132 + ty * 8];
            float4 av1 = *(const float4*)&Ab[k * 132 + ty * 8 + 4];
            ulonglong2 bb0 = *(const ulonglong2*)&Bb[k * 132 + tx * 8];
            ulonglong2 bb1 = *(const ulonglong2*)&Bb[k * 132 + tx * 8 + 4];
            float av[8] = {av0.x, av0.y, av0.z, av0.w, av1.x, av1.y, av1.z, av1.w};
            #pragma unroll
            for (int i = 0; i < 8; i++) {
                unsigned long long ap = pk2(av[i], av[i]);
                fma2(acc[i][0], ap, bb0.x);
                fma2(acc[i][1], ap, bb0.y);
                fma2(acc[i][2], ap, bb1.x);
                fma2(acc[i][3], ap, bb1.y);
            }
        }
        __syncthreads();
        if (more) {
            const float* ap0 = (const float*)&a0r;
            const float* ap1 = (const float*)&a1r;
            float* An = As + (buf ^ 1) * 16 * 132;
            float* Bn = Bs + (buf ^ 1) * 16 * 132;
            #pragma unroll
            for (int j = 0; j < 4; j++) {
                An[(ac + j) * 132 + ar] = ap0[j];
                An[(ac + j) * 132 + ar + 64] = ap1[j];
            }
            *(float4*)&Bn[kb * 132 + n4] = b0r;
            *(float4*)&Bn[(kb + 8) * 132 + n4] = b1r;
            __syncthreads();
        }
    }
    #pragma unroll
    for (int j = 0; j < 4; j++) {
        const int col = n0 + tx * 8 + 2 * j;
        const float bv0 = bias[col], bv1 = bias[col + 1];
        #pragma unroll
        for (int i = 0; i < 8; i++) {
            float2 v = up2(acc[i][j]);
            const int row = m0 + ty * 8 + i;
            g_h[(size_t)row * DDIM + col] = v.x + bv0;
            g_h[(size_t)row * DDIM + col + 1] = v.y + bv1;
        }
    }
}

// ---------------- conversion: fp32 -> (hi, lo) fp16 ----------------
__global__ void convert_h_kernel() {
    int i = blockIdx.x * blockDim.x + threadIdx.x;
    if (i < M_ROWS * DDIM) {
        float v = g_h[i];
        __half hi = __float2half_rn(v);
        g_ahi[i] = hi;
        g_alo[i] = __float2half_rn(v - __half2float(hi));
    }
}
__global__ void convert_cb_kernel(const float* __restrict__ cb) {
    int i = blockIdx.x * blockDim.x + threadIdx.x;
    if (i < K_CODES * DDIM) {
        float v = cb[i];
        __half hi = __float2half_rn(v);
        g_bhi[i] = hi;
        g_blo[i] = __float2half_rn(v - __half2float(hi));
    }
}

// ---------------- kernel 2: mma.sync scoring + fused argmin ----------------
// SMEM: A_hi [0,64K) A_lo [64K,128K): 128 rows x 512B, chunk swizzle c^=(row&7)
//       B [128K,192K): 2 bufs x 2 splits x (128 codes x 128B, sw128)
//       RED [192K, +4K): per-warp row bests [128 rows][4 nwarps] (float,int)
#define SMA_SZ   65536
#define SMB_OFF  131072
#define SMRED    196608
#define SM_TOTAL 200704
#define NSLAB    256     // 64 chunks x 4 slabs

__global__ __launch_bounds__(256, 1) void score_kernel() {
    extern __shared__ __align__(1024) char smem[];
    const uint32_t sb = smem_u32(smem);
    const int tid = threadIdx.x;
    const int wid = tid >> 5;
    const int lane = tid & 31;
    const int mw = wid >> 2;           // 0..1
    const int nw = wid & 3;            // 0..3
    const int tg = lane >> 2;          // 0..7
    const int tq = lane & 3;           // 0..3
    const int m0 = blockIdx.x * 128;

    // ---- preload A (hi+lo) into swizzled smem ----
    #pragma unroll 8
    for (int q = 0; q < 32; q++) {
        const int idx = tid + q * 256;
        const int split = idx >> 12;
        const int rem = idx & 4095;
        const int row = rem >> 5;
        const int c16 = rem & 31;
        const __half* src = (split ? g_alo : g_ahi) + (size_t)(m0 + row) * DDIM + c16 * 8;
        const uint32_t dst = (uint32_t)(split * SMA_SZ + row * 512 + ((c16 ^ (row & 7)) * 16));
        *(uint4*)(smem + dst) = *(const uint4*)src;
    }

    // ---- preload slab 0 (chunk 0, kslab 0) into buf 0 ----
    #pragma unroll
    for (int i = 0; i < 8; i++) {
        const int idx = tid + i * 256;
        const int split = idx >> 10;
        const int rem = idx & 1023;
        const int row = rem >> 3;
        const int c16 = rem & 7;
        const __half* src = (split ? g_blo : g_bhi) + (size_t)row * DDIM + c16 * 8;
        const uint32_t dst = SMB_OFF + split * 16384 + sw128((uint32_t)(row * 128 + c16 * 16));
        *(uint4*)(smem + dst) = *(const uint4*)src;
    }

    // per-thread row bests (8 rows: 4 m-frags x 2 halves)
    float zn8[8], best[8];
    int bidx[8];
    const int rowbase = m0 + mw * 64;
    #pragma unroll
    for (int mf = 0; mf < 4; mf++) {
        zn8[mf * 2]     = g_zn[rowbase + mf * 16 + tg];
        zn8[mf * 2 + 1] = g_zn[rowbase + mf * 16 + tg + 8];
    }
    #pragma unroll
    for (int r = 0; r < 8; r++) { best[r] = 3.402823466e38f; bidx[r] = 0; }

    // ldmatrix A lane geometry
    const int arow = mw * 64 + (lane & 15);
    const uint32_t abase0 = sb + arow * 512;
    const uint32_t abase1 = sb + SMA_SZ + arow * 512;
    const int aswz = arow & 7;
    const int alhalf = lane >> 4;      // 0/1: low/high k-chunk
    // ldmatrix B lane geometry (per n-frag-pair nfp: rows nw*32 + nfp*16 + ...)
    const int brow_in16 = (lane & 7) + ((lane >> 4) << 3);
    const int bksel = (lane >> 3) & 1;

    float acc[4][4][4];
    #pragma unroll
    for (int mf = 0; mf < 4; mf++)
        #pragma unroll
        for (int nf = 0; nf < 4; nf++)
            #pragma unroll
            for (int v = 0; v < 4; v++) acc[mf][nf][v] = 0.0f;

    __syncthreads();

    #pragma unroll 1
    for (int S = 0; S < NSLAB; S++) {
        const int buf = S & 1;
        const bool more = (S + 1 < NSLAB);

        // issue next-slab global loads into registers (hidden under mma)
        uint4 ldreg[8];
        if (more) {
            const int S2 = S + 1;
            const int c2 = S2 >> 2, s2 = S2 & 3;
            #pragma unroll
            for (int i = 0; i < 8; i++) {
                const int idx = tid + i * 256;
                const int split = idx >> 10;
                const int rem = idx & 1023;
                const int row = rem >> 3;
                const int c16 = rem & 7;
                const __half* src = (split ? g_blo : g_bhi)
                    + (size_t)(c2 * 128 + row) * DDIM + s2 * 64 + c16 * 8;
                ldreg[i] = *(const uint4*)src;
            }
        }

        // compute: 4 k16-steps over this slab
        const uint32_t bbhi = sb + SMB_OFF + buf * 32768;
        const uint32_t bblo = bbhi + 16384;
        const int sl = S & 3;
        #pragma unroll
        for (int ks = 0; ks < 4; ks++) {
            const int kchunk = sl * 8 + ks * 2;       // A 16B-chunk index (0..31)
            const uint32_t aoff = (uint32_t)(((kchunk + alhalf) ^ aswz) * 16);
            uint32_t ah[4][4], al[4][4];
            #pragma unroll
            for (int mf = 0; mf < 4; mf++)
                LDSM_X4(ah[mf][0], ah[mf][1], ah[mf][2], ah[mf][3],
                        abase0 + mf * 8192 + aoff);
            // B frags: 2 x4 loads per split cover 4 n-frags
            uint32_t bh[8], bl[8];
            #pragma unroll
            for (int nfp = 0; nfp < 2; nfp++) {
                const int brow = nw * 32 + nfp * 16 + brow_in16;
                const uint32_t bo = sw128((uint32_t)(brow * 128 + (ks * 2 + bksel) * 16));
                LDSM_X4(bh[nfp * 4], bh[nfp * 4 + 1], bh[nfp * 4 + 2], bh[nfp * 4 + 3],
                        bbhi + bo);
                LDSM_X4(bl[nfp * 4], bl[nfp * 4 + 1], bl[nfp * 4 + 2], bl[nfp * 4 + 3],
                        bblo + bo);
            }
            // hi*hi and hi*lo
            #pragma unroll
            for (int mf = 0; mf < 4; mf++)
                #pragma unroll
                for (int nf = 0; nf < 4; nf++) {
                    mma16816(acc[mf][nf], ah[mf], &bh[nf * 2]);
                    mma16816(acc[mf][nf], ah[mf], &bl[nf * 2]);
                }
            // lo*hi
            #pragma unroll
            for (int mf = 0; mf < 4; mf++)
                LDSM_X4(al[mf][0], al[mf][1], al[mf][2], al[mf][3],
                        abase1 + mf * 8192 + aoff);
            #pragma unroll
            for (int mf = 0; mf < 4; mf++)
                #pragma unroll
                for (int nf = 0; nf < 4; nf++)
                    mma16816(acc[mf][nf], al[mf], &bh[nf * 2]);
        }

        // store next slab into other buffer
        if (more) {
            #pragma unroll
            for (int i = 0; i < 8; i++) {
                const int idx = tid + i * 256;
                const int split = idx >> 10;
                const int rem = idx & 1023;
                const int row = rem >> 3;
                const int c16 = rem & 7;
                const uint32_t dst = SMB_OFF + (buf ^ 1) * 32768 + split * 16384
                    + sw128((uint32_t)(row * 128 + c16 * 16));
                *(uint4*)(smem + dst) = ldreg[i];
            }
        }

        // fold completed chunk into running argmin
        if (sl == 3) {
            const int c = S >> 2;
            const int cb0 = c * 128 + nw * 32 + 2 * tq;
            float e0[4], e1[4];
            #pragma unroll
            for (int nf = 0; nf < 4; nf++) {
                e0[nf] = __ldg(&g_en[cb0 + nf * 8]);
                e1[nf] = __ldg(&g_en[cb0 + nf * 8 + 1]);
            }
            #pragma unroll
            for (int mf = 0; mf < 4; mf++) {
                #pragma unroll
                for (int nf = 0; nf < 4; nf++) {
                    float* cc = acc[mf][nf];
                    const int col = cb0 + nf * 8;
                    const float d00 = __fadd_rn(__fadd_rn(zn8[mf * 2], e0[nf]), -2.0f * cc[0]);
                    const float d01 = __fadd_rn(__fadd_rn(zn8[mf * 2], e1[nf]), -2.0f * cc[1]);
                    const float d10 = __fadd_rn(__fadd_rn(zn8[mf * 2 + 1], e0[nf]), -2.0f * cc[2]);
                    const float d11 = __fadd_rn(__fadd_rn(zn8[mf * 2 + 1], e1[nf]), -2.0f * cc[3]);
                    if (d00 < best[mf * 2])     { best[mf * 2] = d00;     bidx[mf * 2] = col; }
                    if (d01 < best[mf * 2])     { best[mf * 2] = d01;     bidx[mf * 2] = col + 1; }
                    if (d10 < best[mf * 2 + 1]) { best[mf * 2 + 1] = d10; bidx[mf * 2 + 1] = col; }
                    if (d11 < best[mf * 2 + 1]) { best[mf * 2 + 1] = d11; bidx[mf * 2 + 1] = col + 1; }
                    cc[0] = 0.0f; cc[1] = 0.0f; cc[2] = 0.0f; cc[3] = 0.0f;
                }
            }
        }
        __syncthreads();
    }

    // reduce across the 4 lanes (tq) sharing each row
    #pragma unroll
    for (int r = 0; r < 8; r++) {
        float bv = best[r];
        int bi = bidx[r];
        #pragma unroll
        for (int off = 1; off <= 2; off <<= 1) {
            const float ov = __shfl_xor_sync(0xffffffffu, bv, off);
            const int   oi = __shfl_xor_sync(0xffffffffu, bi, off);
            if (ov < bv || (ov == bv && oi < bi)) { bv = ov; bi = oi; }
        }
        best[r] = bv;
        bidx[r] = bi;
    }
    if (tq == 0) {
        #pragma unroll
        for (int r = 0; r < 8; r++) {
            const int mf = r >> 1, h = r & 1;
            const int mrow = mw * 64 + mf * 16 + tg + 8 * h;
            *(float*)(smem + SMRED + (mrow * 4 + nw) * 8)     = best[r];
            *(int*)(smem + SMRED + (mrow * 4 + nw) * 8 + 4)   = bidx[r];
        }
    }
    __syncthreads();
    // cross-warp (nw) reduction, ties -> lowest index
    if (tid < 128) {
        float bv = *(float*)(smem + SMRED + (tid * 4) * 8);
        int bi = *(int*)(smem + SMRED + (tid * 4) * 8 + 4);
        #pragma unroll
        for (int n = 1; n < 4; n++) {
            const float v = *(float*)(smem + SMRED + (tid * 4 + n) * 8);
            const int ix = *(int*)(smem + SMRED + (tid * 4 + n) * 8 + 4);
            if (v < bv || (v == bv && ix < bi)) { bv = v; bi = ix; }
        }
        g_idx[m0 + tid] = bi;
    }
}

// ---------------- kernel 3: gather + loss partials ----------------
__global__ void gather_loss_kernel(const float* __restrict__ cb, float* __restrict__ out) {
    const int b = blockIdx.x;
    const int t = threadIdx.x;
    const int base = b * 2048;
    double s = 0.0;
    #pragma unroll
    for (int e = 0; e < 4; e++) {
        const int g = base + t + e * 512;
        const int row = g >> 8;
        const int d = g & 255;
        const int idx = g_idx[row];
        const float c = cb[(size_t)idx * DDIM + d];
        const float h = g_h[g];
        out[g] = c;
        const double diff = (double)(c - h);
        s += diff * diff;
    }
    __shared__ double red[512];
    red[t] = s;
    __syncthreads();
    for (int o = 256; o; o >>= 1) {
        if (t < o) red[t] += red[t + o];
        __syncthreads();
    }
    if (t == 0) g_part[b] = red[0];
}

// ---------------- kernel 4: finalize ----------------
__global__ void finalize_kernel(float* __restrict__ out, int has_loss) {
    __shared__ double red[1024];
    const int t = threadIdx.x;
    double s = 0.0;
    for (int i = t; i < 4096; i += 1024) s += g_part[i];
    red[t] = s;
    __syncthreads();
    for (int o = 512; o; o >>= 1) {
        if (t < o) red[t] += red[t + o];
        __syncthreads();
    }
    if (t == 0 && has_loss)
        out[(size_t)M_ROWS * DDIM] =
            (float)(1.25 * red[0] / (double)((size_t)M_ROWS * DDIM));
}

// ---------------- host launcher ----------------
extern "C" void kernel_launch(void* const* d_in, const int* in_sizes, int n_in,
                              void* d_out, int out_size) {
    const float* x = nullptr;
    const float* W = nullptr;
    const float* b = nullptr;
    const float* cb = nullptr;
    for (int i = 0; i < n_in; i++) {
        switch (in_sizes[i]) {
            case M_ROWS * ZC:    x = (const float*)d_in[i]; break;
            case ZC * DDIM:      W = (const float*)d_in[i]; break;
            case DDIM:           b = (const float*)d_in[i]; break;
            case K_CODES * DDIM: cb = (const float*)d_in[i]; break;
            default: break;
        }
    }
    float* out = (float*)d_out;
    const int has_loss = (out_size > M_ROWS * DDIM) ? 1 : 0;

    cudaFuncSetAttribute(score_kernel, cudaFuncAttributeMaxDynamicSharedMemorySize, SM_TOTAL);

    prep_cb_kernel<<<K_CODES / 8, 256>>>(cb);
    dim3 g1(M_ROWS / 128, DDIM / 128);
    gemm1_kernel<<<g1, 256>>>(x, W, b);
    prep_zn_kernel<<<M_ROWS / 8, 256>>>();
    convert_h_kernel<<<(M_ROWS * DDIM) / 1024, 1024>>>();
    convert_cb_kernel<<<(K_CODES * DDIM) / 1024, 1024>>>(cb);
    score_kernel<<<M_ROWS / 128, 256, SM_TOTAL>>>();
    gather_loss_kernel<<<4096, 512>>>(cb, out);
    finalize_kernel<<<1, 1024>>>(out, has_loss);
}

// round 16
// speedup vs baseline: 3.0233x; 1.1258x over previous
#include <cuda_runtime.h>
#include <cuda_fp16.h>
#include <cstdint>

#define M_ROWS 32768
#define ZC     512
#define DDIM   256
#define K_CODES 8192

// ---------------- device scratch ----------------
__device__ float  g_h[M_ROWS * DDIM];     // 32 MB fp32 h
__device__ __half g_ahi[M_ROWS * DDIM];   // 16 MB
__device__ __half g_alo[M_ROWS * DDIM];   // 16 MB
__device__ __half g_bhi[K_CODES * DDIM];  // 4 MB
__device__ __half g_blo[K_CODES * DDIM];  // 4 MB
__device__ float  g_en[K_CODES];
__device__ float  g_zn[M_ROWS];
__device__ int    g_idx[M_ROWS];
__device__ float  g_cand_d[4][M_ROWS];    // per-quarter best distance
__device__ int    g_cand_i[4][M_ROWS];    // per-quarter best index
__device__ double g_part[4096];

// ---------------- f32x2 helpers (gemm1) ----------------
__device__ __forceinline__ unsigned long long pk2(float lo, float hi) {
    unsigned long long r;
    asm("mov.b64 %0, {%1, %2};" : "=l"(r) : "f"(lo), "f"(hi));
    return r;
}
__device__ __forceinline__ void fma2(unsigned long long &d,
                                     unsigned long long a,
                                     unsigned long long b) {
    asm("fma.rn.f32x2 %0, %1, %2, %0;" : "+l"(d) : "l"(a), "l"(b));
}
__device__ __forceinline__ float2 up2(unsigned long long v) {
    float2 f;
    asm("mov.b64 {%0, %1}, %2;" : "=f"(f.x), "=f"(f.y) : "l"(v));
    return f;
}

__device__ __forceinline__ uint32_t smem_u32(const void* p) {
    uint32_t a;
    asm("{ .reg .u64 t; cvta.to.shared.u64 t, %1; cvt.u32.u64 %0, t; }" : "=r"(a) : "l"(p));
    return a;
}
__device__ __forceinline__ uint32_t sw128(uint32_t b) { return b ^ ((b >> 3) & 0x70); }

#define LDSM_X4(r0, r1, r2, r3, addr) \
    asm volatile("ldmatrix.sync.aligned.m8n8.x4.shared.b16 {%0,%1,%2,%3}, [%4];" \
                 : "=r"(r0), "=r"(r1), "=r"(r2), "=r"(r3) : "r"(addr))

__device__ __forceinline__ void mma16816(float* c, const uint32_t* a, const uint32_t* b) {
    asm volatile("mma.sync.aligned.m16n8k16.row.col.f32.f16.f16.f32 "
                 "{%0,%1,%2,%3}, {%4,%5,%6,%7}, {%8,%9}, {%0,%1,%2,%3};"
                 : "+f"(c[0]), "+f"(c[1]), "+f"(c[2]), "+f"(c[3])
                 : "r"(a[0]), "r"(a[1]), "r"(a[2]), "r"(a[3]), "r"(b[0]), "r"(b[1]));
}

#define CP_ASYNC16(dst, src) \
    asm volatile("cp.async.cg.shared.global [%0], [%1], 16;" :: "r"(dst), "l"(src) : "memory")
#define CP_COMMIT() asm volatile("cp.async.commit_group;" ::: "memory")
#define CP_WAIT1()  asm volatile("cp.async.wait_group 1;" ::: "memory")
#define CP_WAIT0()  asm volatile("cp.async.wait_group 0;" ::: "memory")

// ---------------- kernel 0a: codebook norms ----------------
__global__ void prep_cb_kernel(const float* __restrict__ cb) {
    int warp = (blockIdx.x * blockDim.x + threadIdx.x) >> 5;
    int lane = threadIdx.x & 31;
    if (warp < K_CODES) {
        const float* row = cb + (size_t)warp * DDIM;
        double s = 0.0;
        #pragma unroll
        for (int d = 0; d < DDIM / 32; d++) {
            double v = (double)row[lane + 32 * d];
            s += v * v;
        }
        #pragma unroll
        for (int o = 16; o; o >>= 1) s += __shfl_xor_sync(0xffffffffu, s, o);
        if (lane == 0) g_en[warp] = (float)s;
    }
}

// ---------------- kernel 0b: h row norms ----------------
__global__ void prep_zn_kernel() {
    int warp = (blockIdx.x * blockDim.x + threadIdx.x) >> 5;
    int lane = threadIdx.x & 31;
    if (warp < M_ROWS) {
        const float* row = g_h + (size_t)warp * DDIM;
        double s = 0.0;
        #pragma unroll
        for (int d = 0; d < DDIM / 32; d++) {
            double v = (double)row[lane + 32 * d];
            s += v * v;
        }
        #pragma unroll
        for (int o = 16; o; o >>= 1) s += __shfl_xor_sync(0xffffffffu, s, o);
        if (lane == 0) g_zn[warp] = (float)s;
    }
}

// ---------------- kernel 1: h = x@W + b (fp32) + fused fp16 split ----------------
__global__ __launch_bounds__(256) void gemm1_kernel(const float* __restrict__ X,
                                                    const float* __restrict__ Wm,
                                                    const float* __restrict__ bias) {
    __shared__ __align__(16) float sm[2 * 16 * 132 * 2];
    float* As = sm;
    float* Bs = sm + 2 * 16 * 132;
    const int m0 = blockIdx.x * 128;
    const int n0 = blockIdx.y * 128;
    const int tid = threadIdx.x;
    const int ty = tid >> 4, tx = tid & 15;

    unsigned long long acc[8][4];
    #pragma unroll
    for (int i = 0; i < 8; i++)
        #pragma unroll
        for (int j = 0; j < 4; j++) acc[i][j] = 0ull;

    const int ar = tid >> 2, ac = (tid & 3) << 2;
    const int kb = tid >> 5, n4 = (tid & 31) << 2;
    const int NS = ZC / 16;
    float4 a0r, a1r, b0r, b1r;
    {
        a0r = *(const float4*)(X + (size_t)(m0 + ar) * ZC + ac);
        a1r = *(const float4*)(X + (size_t)(m0 + ar + 64) * ZC + ac);
        b0r = *(const float4*)(Wm + (size_t)kb * DDIM + n0 + n4);
        b1r = *(const float4*)(Wm + (size_t)(kb + 8) * DDIM + n0 + n4);
        const float* ap0 = (const float*)&a0r;
        const float* ap1 = (const float*)&a1r;
        #pragma unroll
        for (int j = 0; j < 4; j++) {
            As[(ac + j) * 132 + ar] = ap0[j];
            As[(ac + j) * 132 + ar + 64] = ap1[j];
        }
        *(float4*)&Bs[kb * 132 + n4] = b0r;
        *(float4*)&Bs[(kb + 8) * 132 + n4] = b1r;
    }
    __syncthreads();
    #pragma unroll 1
    for (int s = 0; s < NS; s++) {
        const int buf = s & 1;
        const bool more = (s + 1 < NS);
        if (more) {
            const int kk = (s + 1) << 4;
            a0r = *(const float4*)(X + (size_t)(m0 + ar) * ZC + kk + ac);
            a1r = *(const float4*)(X + (size_t)(m0 + ar + 64) * ZC + kk + ac);
            b0r = *(const float4*)(Wm + (size_t)(kk + kb) * DDIM + n0 + n4);
            b1r = *(const float4*)(Wm + (size_t)(kk + kb + 8) * DDIM + n0 + n4);
        }
        const float* Ab = As + buf * 16 * 132;
        const float* Bb = Bs + buf * 16 * 132;
        #pragma unroll
        for (int k = 0; k < 16; k++) {
            float4 av0 = *(const float4*)&Ab[k * 132 + ty * 8];
            float4 av1 = *(const float4*)&Ab[k * 132 + ty * 8 + 4];
            ulonglong2 bb0 = *(const ulonglong2*)&Bb[k * 132 + tx * 8];
            ulonglong2 bb1 = *(const ulonglong2*)&Bb[k * 132 + tx * 8 + 4];
            float av[8] = {av0.x, av0.y, av0.z, av0.w, av1.x, av1.y, av1.z, av1.w};
            #pragma unroll
            for (int i = 0; i < 8; i++) {
                unsigned long long ap = pk2(av[i], av[i]);
                fma2(acc[i][0], ap, bb0.x);
                fma2(acc[i][1], ap, bb0.y);
                fma2(acc[i][2], ap, bb1.x);
                fma2(acc[i][3], ap, bb1.y);
            }
        }
        __syncthreads();
        if (more) {
            const float* ap0 = (const float*)&a0r;
            const float* ap1 = (const float*)&a1r;
            float* An = As + (buf ^ 1) * 16 * 132;
            float* Bn = Bs + (buf ^ 1) * 16 * 132;
            #pragma unroll
            for (int j = 0; j < 4; j++) {
                An[(ac + j) * 132 + ar] = ap0[j];
                An[(ac + j) * 132 + ar + 64] = ap1[j];
            }
            *(float4*)&Bn[kb * 132 + n4] = b0r;
            *(float4*)&Bn[(kb + 8) * 132 + n4] = b1r;
            __syncthreads();
        }
    }
    #pragma unroll
    for (int j = 0; j < 4; j++) {
        const int col = n0 + tx * 8 + 2 * j;
        const float bv0 = bias[col], bv1 = bias[col + 1];
        #pragma unroll
        for (int i = 0; i < 8; i++) {
            float2 v = up2(acc[i][j]);
            const int row = m0 + ty * 8 + i;
            const float h0 = v.x + bv0;
            const float h1 = v.y + bv1;
            const size_t p = (size_t)row * DDIM + col;
            g_h[p]     = h0;
            g_h[p + 1] = h1;
            const __half hi0 = __float2half_rn(h0);
            const __half hi1 = __float2half_rn(h1);
            g_ahi[p]     = hi0;
            g_ahi[p + 1] = hi1;
            g_alo[p]     = __float2half_rn(h0 - __half2float(hi0));
            g_alo[p + 1] = __float2half_rn(h1 - __half2float(hi1));
        }
    }
}

// ---------------- conversion: codebook fp32 -> (hi, lo) fp16 ----------------
__global__ void convert_cb_kernel(const float* __restrict__ cb) {
    int i = blockIdx.x * blockDim.x + threadIdx.x;
    if (i < K_CODES * DDIM) {
        float v = cb[i];
        __half hi = __float2half_rn(v);
        g_bhi[i] = hi;
        g_blo[i] = __float2half_rn(v - __half2float(hi));
    }
}

// ---------------- kernel 2: mma.sync scoring + fused argmin (code-split 4x) ----------------
// grid = (M/128, 4). Each CTA: 128 rows x 2048 codes.
// SMEM: A_hi [0,64K) A_lo [64K,128K): 128 rows x 512B, chunk swizzle c^=(row&7)
//       B [128K,192K): 2 bufs x 2 splits x (128 codes x 128B, sw128)
//       RED [192K, +4K)
#define SMA_SZ   65536
#define SMB_OFF  131072
#define SMRED    196608
#define SM_TOTAL 200704
#define NSLAB    64      // 16 chunks x 4 slabs (2048 codes per CTA)

__global__ __launch_bounds__(256, 1) void score_kernel() {
    extern __shared__ __align__(1024) char smem[];
    const uint32_t sb = smem_u32(smem);
    const int tid = threadIdx.x;
    const int wid = tid >> 5;
    const int lane = tid & 31;
    const int mw = wid >> 2;           // 0..1
    const int nw = wid & 3;            // 0..3
    const int tg = lane >> 2;          // 0..7
    const int tq = lane & 3;           // 0..3
    const int m0 = blockIdx.x * 128;
    const int q  = blockIdx.y;         // code quarter 0..3
    const int kc0 = q * 2048;

    // ---- prologue: issue slab 0 (chunk kc0, kslab 0) into buf 0 via cp.async ----
    #pragma unroll
    for (int i = 0; i < 8; i++) {
        const int idx = tid + i * 256;
        const int split = idx >> 10;
        const int rem = idx & 1023;
        const int row = rem >> 3;
        const int c16 = rem & 7;
        const __half* src = (split ? g_blo : g_bhi) + (size_t)(kc0 + row) * DDIM + c16 * 8;
        const uint32_t dst = sb + SMB_OFF + split * 16384 + sw128((uint32_t)(row * 128 + c16 * 16));
        CP_ASYNC16(dst, src);
    }
    CP_COMMIT();

    // ---- preload A (hi+lo) into swizzled smem ----
    #pragma unroll 8
    for (int p = 0; p < 32; p++) {
        const int idx = tid + p * 256;
        const int split = idx >> 12;
        const int rem = idx & 4095;
        const int row = rem >> 5;
        const int c16 = rem & 31;
        const __half* src = (split ? g_alo : g_ahi) + (size_t)(m0 + row) * DDIM + c16 * 8;
        const uint32_t dst = (uint32_t)(split * SMA_SZ + row * 512 + ((c16 ^ (row & 7)) * 16));
        *(uint4*)(smem + dst) = *(const uint4*)src;
    }

    // per-thread row bests (8 rows: 4 m-frags x 2 halves)
    float zn8[8], best[8];
    int bidx[8];
    const int rowbase = m0 + mw * 64;
    #pragma unroll
    for (int mf = 0; mf < 4; mf++) {
        zn8[mf * 2]     = g_zn[rowbase + mf * 16 + tg];
        zn8[mf * 2 + 1] = g_zn[rowbase + mf * 16 + tg + 8];
    }
    #pragma unroll
    for (int r = 0; r < 8; r++) { best[r] = 3.402823466e38f; bidx[r] = 0; }

    // ldmatrix A lane geometry
    const int arow = mw * 64 + (lane & 15);
    const uint32_t abase0 = sb + arow * 512;
    const uint32_t abase1 = sb + SMA_SZ + arow * 512;
    const int aswz = arow & 7;
    const int alhalf = lane >> 4;
    // ldmatrix B lane geometry
    const int brow_in16 = (lane & 7) + ((lane >> 4) << 3);
    const int bksel = (lane >> 3) & 1;

    float acc[4][4][4];
    #pragma unroll
    for (int mf = 0; mf < 4; mf++)
        #pragma unroll
        for (int nf = 0; nf < 4; nf++)
            #pragma unroll
            for (int v = 0; v < 4; v++) acc[mf][nf][v] = 0.0f;

    #pragma unroll 1
    for (int S = 0; S < NSLAB; S++) {
        const int buf = S & 1;
        const bool more = (S + 1 < NSLAB);

        if (more) {
            const int S2 = S + 1;
            const int c2 = S2 >> 2, s2 = S2 & 3;
            #pragma unroll
            for (int i = 0; i < 8; i++) {
                const int idx = tid + i * 256;
                const int split = idx >> 10;
                const int rem = idx & 1023;
                const int row = rem >> 3;
                const int c16 = rem & 7;
                const __half* src = (split ? g_blo : g_bhi)
                    + (size_t)(kc0 + c2 * 128 + row) * DDIM + s2 * 64 + c16 * 8;
                const uint32_t dst = sb + SMB_OFF + (buf ^ 1) * 32768 + split * 16384
                    + sw128((uint32_t)(row * 128 + c16 * 16));
                CP_ASYNC16(dst, src);
            }
            CP_COMMIT();
            CP_WAIT1();
        } else {
            CP_WAIT0();
        }
        __syncthreads();   // slab S visible (and A preload on first iter)

        // compute: 4 k16-steps over this slab
        const uint32_t bbhi = sb + SMB_OFF + buf * 32768;
        const uint32_t bblo = bbhi + 16384;
        const int sl = S & 3;
        #pragma unroll
        for (int ks = 0; ks < 4; ks++) {
            const int kchunk = sl * 8 + ks * 2;
            const uint32_t aoff = (uint32_t)(((kchunk + alhalf) ^ aswz) * 16);
            uint32_t ah[4][4], al[4][4];
            #pragma unroll
            for (int mf = 0; mf < 4; mf++)
                LDSM_X4(ah[mf][0], ah[mf][1], ah[mf][2], ah[mf][3],
                        abase0 + mf * 8192 + aoff);
            uint32_t bh[8], bl[8];
            #pragma unroll
            for (int nfp = 0; nfp < 2; nfp++) {
                const int brow = nw * 32 + nfp * 16 + brow_in16;
                const uint32_t bo = sw128((uint32_t)(brow * 128 + (ks * 2 + bksel) * 16));
                LDSM_X4(bh[nfp * 4], bh[nfp * 4 + 1], bh[nfp * 4 + 2], bh[nfp * 4 + 3],
                        bbhi + bo);
                LDSM_X4(bl[nfp * 4], bl[nfp * 4 + 1], bl[nfp * 4 + 2], bl[nfp * 4 + 3],
                        bblo + bo);
            }
            #pragma unroll
            for (int mf = 0; mf < 4; mf++)
                #pragma unroll
                for (int nf = 0; nf < 4; nf++) {
                    mma16816(acc[mf][nf], ah[mf], &bh[nf * 2]);
                    mma16816(acc[mf][nf], ah[mf], &bl[nf * 2]);
                }
            #pragma unroll
            for (int mf = 0; mf < 4; mf++)
                LDSM_X4(al[mf][0], al[mf][1], al[mf][2], al[mf][3],
                        abase1 + mf * 8192 + aoff);
            #pragma unroll
            for (int mf = 0; mf < 4; mf++)
                #pragma unroll
                for (int nf = 0; nf < 4; nf++)
                    mma16816(acc[mf][nf], al[mf], &bh[nf * 2]);
        }

        // fold completed chunk into running argmin
        if (sl == 3) {
            const int c = S >> 2;
            const int cb0 = kc0 + c * 128 + nw * 32 + 2 * tq;
            float e0[4], e1[4];
            #pragma unroll
            for (int nf = 0; nf < 4; nf++) {
                e0[nf] = __ldg(&g_en[cb0 + nf * 8]);
                e1[nf] = __ldg(&g_en[cb0 + nf * 8 + 1]);
            }
            #pragma unroll
            for (int mf = 0; mf < 4; mf++) {
                #pragma unroll
                for (int nf = 0; nf < 4; nf++) {
                    float* cc = acc[mf][nf];
                    const int col = cb0 + nf * 8;
                    const float d00 = __fadd_rn(__fadd_rn(zn8[mf * 2], e0[nf]), -2.0f * cc[0]);
                    const float d01 = __fadd_rn(__fadd_rn(zn8[mf * 2], e1[nf]), -2.0f * cc[1]);
                    const float d10 = __fadd_rn(__fadd_rn(zn8[mf * 2 + 1], e0[nf]), -2.0f * cc[2]);
                    const float d11 = __fadd_rn(__fadd_rn(zn8[mf * 2 + 1], e1[nf]), -2.0f * cc[3]);
                    if (d00 < best[mf * 2])     { best[mf * 2] = d00;     bidx[mf * 2] = col; }
                    if (d01 < best[mf * 2])     { best[mf * 2] = d01;     bidx[mf * 2] = col + 1; }
                    if (d10 < best[mf * 2 + 1]) { best[mf * 2 + 1] = d10; bidx[mf * 2 + 1] = col; }
                    if (d11 < best[mf * 2 + 1]) { best[mf * 2 + 1] = d11; bidx[mf * 2 + 1] = col + 1; }
                    cc[0] = 0.0f; cc[1] = 0.0f; cc[2] = 0.0f; cc[3] = 0.0f;
                }
            }
        }
        __syncthreads();   // all reads of buf S done before next issue reuses it
    }

    // reduce across the 4 lanes (tq) sharing each row
    #pragma unroll
    for (int r = 0; r < 8; r++) {
        float bv = best[r];
        int bi = bidx[r];
        #pragma unroll
        for (int off = 1; off <= 2; off <<= 1) {
            const float ov = __shfl_xor_sync(0xffffffffu, bv, off);
            const int   oi = __shfl_xor_sync(0xffffffffu, bi, off);
            if (ov < bv || (ov == bv && oi < bi)) { bv = ov; bi = oi; }
        }
        best[r] = bv;
        bidx[r] = bi;
    }
    if (tq == 0) {
        #pragma unroll
        for (int r = 0; r < 8; r++) {
            const int mf = r >> 1, h = r & 1;
            const int mrow = mw * 64 + mf * 16 + tg + 8 * h;
            *(float*)(smem + SMRED + (mrow * 4 + nw) * 8)   = best[r];
            *(int*)(smem + SMRED + (mrow * 4 + nw) * 8 + 4) = bidx[r];
        }
    }
    __syncthreads();
    // cross-warp (nw) reduction, ties -> lowest index; write quarter candidate
    if (tid < 128) {
        float bv = *(float*)(smem + SMRED + (tid * 4) * 8);
        int bi = *(int*)(smem + SMRED + (tid * 4) * 8 + 4);
        #pragma unroll
        for (int n = 1; n < 4; n++) {
            const float v = *(float*)(smem + SMRED + (tid * 4 + n) * 8);
            const int ix = *(int*)(smem + SMRED + (tid * 4 + n) * 8 + 4);
            if (v < bv || (v == bv && ix < bi)) { bv = v; bi = ix; }
        }
        g_cand_d[q][m0 + tid] = bv;
        g_cand_i[q][m0 + tid] = bi;
    }
}

// ---------------- kernel 2b: merge quarter candidates ----------------
__global__ void merge_kernel() {
    const int r = blockIdx.x * blockDim.x + threadIdx.x;
    if (r < M_ROWS) {
        float bv = g_cand_d[0][r];
        int bi = g_cand_i[0][r];
        #pragma unroll
        for (int q = 1; q < 4; q++) {
            const float v = g_cand_d[q][r];
            const int ix = g_cand_i[q][r];
            // quarters have disjoint ascending index ranges: strict < keeps
            // the lowest-index (first-occurrence) winner on ties.
            if (v < bv) { bv = v; bi = ix; }
        }
        g_idx[r] = bi;
    }
}

// ---------------- kernel 3: gather + loss partials ----------------
__global__ void gather_loss_kernel(const float* __restrict__ cb, float* __restrict__ out) {
    const int b = blockIdx.x;
    const int t = threadIdx.x;
    const int base = b * 2048;
    double s = 0.0;
    #pragma unroll
    for (int e = 0; e < 4; e++) {
        const int g = base + t + e * 512;
        const int row = g >> 8;
        const int d = g & 255;
        const int idx = g_idx[row];
        const float c = cb[(size_t)idx * DDIM + d];
        const float h = g_h[g];
        out[g] = c;
        const double diff = (double)(c - h);
        s += diff * diff;
    }
    __shared__ double red[512];
    red[t] = s;
    __syncthreads();
    for (int o = 256; o; o >>= 1) {
        if (t < o) red[t] += red[t + o];
        __syncthreads();
    }
    if (t == 0) g_part[b] = red[0];
}

// ---------------- kernel 4: finalize ----------------
__global__ void finalize_kernel(float* __restrict__ out, int has_loss) {
    __shared__ double red[1024];
    const int t = threadIdx.x;
    double s = 0.0;
    for (int i = t; i < 4096; i += 1024) s += g_part[i];
    red[t] = s;
    __syncthreads();
    for (int o = 512; o; o >>= 1) {
        if (t < o) red[t] += red[t + o];
        __syncthreads();
    }
    if (t == 0 && has_loss)
        out[(size_t)M_ROWS * DDIM] =
            (float)(1.25 * red[0] / (double)((size_t)M_ROWS * DDIM));
}

// ---------------- host launcher ----------------
extern "C" void kernel_launch(void* const* d_in, const int* in_sizes, int n_in,
                              void* d_out, int out_size) {
    const float* x = nullptr;
    const float* W = nullptr;
    const float* b = nullptr;
    const float* cb = nullptr;
    for (int i = 0; i < n_in; i++) {
        switch (in_sizes[i]) {
            case M_ROWS * ZC:    x = (const float*)d_in[i]; break;
            case ZC * DDIM:      W = (const float*)d_in[i]; break;
            case DDIM:           b = (const float*)d_in[i]; break;
            case K_CODES * DDIM: cb = (const float*)d_in[i]; break;
            default: break;
        }
    }
    float* out = (float*)d_out;
    const int has_loss = (out_size > M_ROWS * DDIM) ? 1 : 0;

    cudaFuncSetAttribute(score_kernel, cudaFuncAttributeMaxDynamicSharedMemorySize, SM_TOTAL);

    prep_cb_kernel<<<K_CODES / 8, 256>>>(cb);
    convert_cb_kernel<<<(K_CODES * DDIM) / 1024, 1024>>>(cb);
    dim3 g1(M_ROWS / 128, DDIM / 128);
    gemm1_kernel<<<g1, 256>>>(x, W, b);
    prep_zn_kernel<<<M_ROWS / 8, 256>>>();
    dim3 gs(M_ROWS / 128, 4);
    score_kernel<<<gs, 256, SM_TOTAL>>>();
    merge_kernel<<<M_ROWS / 256, 256>>>();
    gather_loss_kernel<<<4096, 512>>>(cb, out);
    finalize_kernel<<<1, 1024>>>(out, has_loss);
}